// round 1
// baseline (speedup 1.0000x reference)
#include <cuda_runtime.h>

#define NN 100000
#define F 128

// Scratch (no cudaMalloc allowed): scaled projected features + degrees + dtype flag.
__device__ float g_xs[(size_t)NN * F];   // 51.2 MB
__device__ float g_deg[NN];
__device__ int   g_is64;

// ---------------------------------------------------------------------------
// Detect whether edge_index is int64 or int32 (JAX x64 flag ambiguity).
// If the buffer really is int64, every 8-byte value is a valid index in
// [0, NN). If it is int32, an 8-byte read combines two indices and the high
// half is almost surely nonzero -> value out of range.
// Deterministic: depends only on input bytes.
// ---------------------------------------------------------------------------
__global__ void detect_kernel(const long long* __restrict__ ei) {
    if (blockIdx.x == 0 && threadIdx.x == 0) {
        int is64 = 1;
        #pragma unroll 1
        for (int i = 0; i < 64; i++) {
            long long v = ei[i];
            if (v < 0 || v >= (long long)NN) { is64 = 0; break; }
        }
        g_is64 = is64;
    }
}

__device__ __forceinline__ int load_idx(const void* ei, long long i, int is64) {
    if (is64) return (int)((const long long*)ei)[i];
    return ((const int*)ei)[i];
}

// ---------------------------------------------------------------------------
// Degree: deg = 1 (self loop) + count of occurrences in col = edge_index[1].
// ---------------------------------------------------------------------------
__global__ void init_deg_kernel() {
    int i = blockIdx.x * blockDim.x + threadIdx.x;
    if (i < NN) g_deg[i] = 1.0f;
}

__global__ void degree_kernel(const void* __restrict__ ei, int E) {
    int e = blockIdx.x * blockDim.x + threadIdx.x;
    if (e >= E) return;
    int is64 = g_is64;
    int c = load_idx(ei, (long long)E + e, is64);
    atomicAdd(&g_deg[c], 1.0f);
}

// ---------------------------------------------------------------------------
// GEMM: g_xs[i] = rsqrt(deg[i]) * (X[i] @ W^T); also initializes d_out with the
// same values (the self-loop contribution before the final dinv[r] scale).
// Tile: 32 rows x 128 cols per 256-thread block, k-tiled by 32.
// Each thread computes a 4x4 register tile.
// ---------------------------------------------------------------------------
__global__ void gemm_kernel(const float* __restrict__ X,
                            const float* __restrict__ W,
                            float* __restrict__ out) {
    __shared__ float Xs[32][32];    // [kk][row]
    __shared__ float Ws[32][128];   // [kk][col]

    int t = threadIdx.x;
    int block_row = blockIdx.x * 32;
    int cg = t & 31;        // column group (warp lane)
    int rg = t >> 5;        // row group (warp id)
    int c0 = cg * 4;
    int r0 = rg * 4;

    float acc[4][4];
    #pragma unroll
    for (int i = 0; i < 4; i++)
        #pragma unroll
        for (int j = 0; j < 4; j++) acc[i][j] = 0.0f;

    for (int k0 = 0; k0 < F; k0 += 32) {
        // Stage X tile (32 rows x 32 k), transposed into Xs[kk][row].
        {
            int row  = t >> 3;
            int kk   = (t & 7) << 2;
            int grow = block_row + row;
            float4 v = make_float4(0.f, 0.f, 0.f, 0.f);
            if (grow < NN) v = *(const float4*)&X[(size_t)grow * F + k0 + kk];
            Xs[kk + 0][row] = v.x;
            Xs[kk + 1][row] = v.y;
            Xs[kk + 2][row] = v.z;
            Xs[kk + 3][row] = v.w;
        }
        // Stage W tile (all 128 j, 32 k), transposed into Ws[kk][j].
        #pragma unroll
        for (int i = 0; i < 4; i++) {
            int idx = t + i * 256;
            int j   = idx >> 3;
            int kk  = (idx & 7) << 2;
            float4 w = *(const float4*)&W[(size_t)j * F + k0 + kk];
            Ws[kk + 0][j] = w.x;
            Ws[kk + 1][j] = w.y;
            Ws[kk + 2][j] = w.z;
            Ws[kk + 3][j] = w.w;
        }
        __syncthreads();

        #pragma unroll
        for (int kk = 0; kk < 32; kk++) {
            float4 xv = *(const float4*)&Xs[kk][r0];   // broadcast within warp
            float4 wv = *(const float4*)&Ws[kk][c0];   // conflict-free
            acc[0][0] += xv.x * wv.x; acc[0][1] += xv.x * wv.y;
            acc[0][2] += xv.x * wv.z; acc[0][3] += xv.x * wv.w;
            acc[1][0] += xv.y * wv.x; acc[1][1] += xv.y * wv.y;
            acc[1][2] += xv.y * wv.z; acc[1][3] += xv.y * wv.w;
            acc[2][0] += xv.z * wv.x; acc[2][1] += xv.z * wv.y;
            acc[2][2] += xv.z * wv.z; acc[2][3] += xv.z * wv.w;
            acc[3][0] += xv.w * wv.x; acc[3][1] += xv.w * wv.y;
            acc[3][2] += xv.w * wv.z; acc[3][3] += xv.w * wv.w;
        }
        __syncthreads();
    }

    #pragma unroll
    for (int i = 0; i < 4; i++) {
        int r = block_row + r0 + i;
        if (r < NN) {
            float s = rsqrtf(g_deg[r]);
            float4 o = make_float4(acc[i][0] * s, acc[i][1] * s,
                                   acc[i][2] * s, acc[i][3] * s);
            *(float4*)&g_xs[(size_t)r * F + c0] = o;
            *(float4*)&out [(size_t)r * F + c0] = o;
        }
    }
}

// ---------------------------------------------------------------------------
// Scatter: one warp per edge. out[row] += g_xs[col]  (128 floats / edge).
// Gather is LDG.128; accumulate is red.global.add.v4.f32 (L2-resident RMW).
// ---------------------------------------------------------------------------
__global__ void scatter_kernel(const void* __restrict__ ei, int E,
                               float* __restrict__ out) {
    long long gtid = (long long)blockIdx.x * blockDim.x + threadIdx.x;
    long long e = gtid >> 5;
    int lane = threadIdx.x & 31;
    if (e >= E) return;
    int is64 = g_is64;
    int r = load_idx(ei, e, is64);
    int c = load_idx(ei, (long long)E + e, is64);

    float4 v = *(const float4*)&g_xs[(size_t)c * F + lane * 4];
    float* dst = &out[(size_t)r * F + lane * 4];
    asm volatile("red.global.add.v4.f32 [%0], {%1, %2, %3, %4};"
                 :: "l"(dst), "f"(v.x), "f"(v.y), "f"(v.z), "f"(v.w)
                 : "memory");
}

// ---------------------------------------------------------------------------
// Final scale: out[r] *= rsqrt(deg[r]).
// ---------------------------------------------------------------------------
__global__ void scale_kernel(float* __restrict__ out) {
    int i = blockIdx.x * blockDim.x + threadIdx.x;  // over NN*32 float4s
    if (i < NN * 32) {
        int r = i >> 5;
        float s = rsqrtf(g_deg[r]);
        float4 v = ((float4*)out)[i];
        v.x *= s; v.y *= s; v.z *= s; v.w *= s;
        ((float4*)out)[i] = v;
    }
}

extern "C" void kernel_launch(void* const* d_in, const int* in_sizes, int n_in,
                              void* d_out, int out_size) {
    const float* X  = (const float*)d_in[0];
    const float* W  = (const float*)d_in[1];
    const void*  ei = d_in[2];
    int E = in_sizes[2] / 2;
    float* out = (float*)d_out;

    detect_kernel<<<1, 32>>>((const long long*)ei);
    init_deg_kernel<<<(NN + 255) / 256, 256>>>();
    degree_kernel<<<(E + 255) / 256, 256>>>(ei, E);
    gemm_kernel<<<(NN + 31) / 32, 256>>>(X, W, out);
    {
        long long total = (long long)E * 32;
        int blocks = (int)((total + 255) / 256);
        scatter_kernel<<<blocks, 256>>>(ei, E, out);
    }
    scale_kernel<<<(NN * 32 + 255) / 256, 256>>>(out);
}

// round 2
// speedup vs baseline: 1.7537x; 1.7537x over previous
#include <cuda_runtime.h>

#define NN   100000
#define F    128
#define EMAX 1700000
#define NB   ((NN + 255) / 256)   // 391 scan blocks

// ---- scratch (no cudaMalloc allowed) --------------------------------------
__device__ float g_xs[(size_t)NN * F];   // dinv[i] * (X[i] @ W^T)   (51.2 MB)
__device__ float g_deg[NN];              // 1 + count(col)
__device__ int   g_cnt[NN];              // count(row)  (CSR bucket sizes)
__device__ int   g_cur[NN];              // CSR fill cursors
__device__ int   g_offs[NN + 1];         // CSR offsets
__device__ int   g_part[NB];             // scan partials
__device__ int   g_partx[NB];            // exclusive-scanned partials
__device__ int   g_csr[EMAX];            // CSR column indices
__device__ int   g_is64;

// ---------------------------------------------------------------------------
// int64 vs int32 edge_index sniffing (deterministic on input bytes).
// ---------------------------------------------------------------------------
__global__ void detect_kernel(const long long* __restrict__ ei) {
    if (blockIdx.x == 0 && threadIdx.x == 0) {
        int is64 = 1;
        #pragma unroll 1
        for (int i = 0; i < 64; i++) {
            long long v = ei[i];
            if (v < 0 || v >= (long long)NN) { is64 = 0; break; }
        }
        g_is64 = is64;
    }
}

__device__ __forceinline__ int load_idx(const void* ei, long long i, int is64) {
    if (is64) return (int)((const long long*)ei)[i];
    return ((const int*)ei)[i];
}

// ---------------------------------------------------------------------------
// init: deg = 1 (self loop), cnt = cur = 0
// ---------------------------------------------------------------------------
__global__ void init_kernel() {
    int i = blockIdx.x * blockDim.x + threadIdx.x;
    if (i < NN) { g_deg[i] = 1.0f; g_cnt[i] = 0; g_cur[i] = 0; }
}

// ---------------------------------------------------------------------------
// histogram: deg[col]++ (float, for rsqrt), cnt[row]++ (int, CSR sizes)
// ---------------------------------------------------------------------------
__global__ void hist_kernel(const void* __restrict__ ei, int E) {
    int e = blockIdx.x * blockDim.x + threadIdx.x;
    if (e >= E) return;
    int is64 = g_is64;
    int r = load_idx(ei, e, is64);
    int c = load_idx(ei, (long long)E + e, is64);
    atomicAdd(&g_deg[c], 1.0f);
    atomicAdd(&g_cnt[r], 1);
}

// ---------------------------------------------------------------------------
// 3-kernel exclusive scan of g_cnt -> g_offs
// ---------------------------------------------------------------------------
__global__ void scan_part_kernel() {
    __shared__ int sm[256];
    int t = threadIdx.x;
    int i = blockIdx.x * 256 + t;
    sm[t] = (i < NN) ? g_cnt[i] : 0;
    __syncthreads();
    for (int s = 128; s > 0; s >>= 1) {
        if (t < s) sm[t] += sm[t + s];
        __syncthreads();
    }
    if (t == 0) g_part[blockIdx.x] = sm[0];
}

__global__ void scan_top_kernel() {
    __shared__ int sm[512];
    int t = threadIdx.x;
    int v = (t < NB) ? g_part[t] : 0;
    sm[t] = v;
    __syncthreads();
    for (int off = 1; off < 512; off <<= 1) {
        int add = (t >= off) ? sm[t - off] : 0;
        __syncthreads();
        sm[t] += add;
        __syncthreads();
    }
    if (t < NB) g_partx[t] = sm[t] - v;           // exclusive
    if (t == NB - 1) g_offs[NN] = sm[t];          // total = E
}

__global__ void scan_final_kernel() {
    __shared__ int sm[256];
    int t = threadIdx.x;
    int i = blockIdx.x * 256 + t;
    int v = (i < NN) ? g_cnt[i] : 0;
    sm[t] = v;
    __syncthreads();
    for (int off = 1; off < 256; off <<= 1) {
        int add = (t >= off) ? sm[t - off] : 0;
        __syncthreads();
        sm[t] += add;
        __syncthreads();
    }
    if (i < NN) g_offs[i] = g_partx[blockIdx.x] + sm[t] - v;  // exclusive
}

// ---------------------------------------------------------------------------
// CSR bucket fill: csr[offs[r] + pos] = c
// ---------------------------------------------------------------------------
__global__ void fill_kernel(const void* __restrict__ ei, int E) {
    int e = blockIdx.x * blockDim.x + threadIdx.x;
    if (e >= E) return;
    int is64 = g_is64;
    int r = load_idx(ei, e, is64);
    int c = load_idx(ei, (long long)E + e, is64);
    int pos = atomicAdd(&g_cur[r], 1);
    g_csr[g_offs[r] + pos] = c;
}

// ---------------------------------------------------------------------------
// GEMM: g_xs[i] = rsqrt(deg[i]) * (X[i] @ W^T)
// 128x128 block tile, 256 threads, 8x8 register tile, k-tile 16.
// Column/row quadrants at +0/+64 to keep LDS.128 b-frag reads conflict-free.
// ---------------------------------------------------------------------------
__global__ void __launch_bounds__(256)
gemm_kernel(const float* __restrict__ X, const float* __restrict__ W) {
    __shared__ float Xs[16][128];
    __shared__ float Ws[16][128];

    int t = threadIdx.x;
    int brow = blockIdx.x * 128;
    int tx = t & 15;      // col group
    int ty = t >> 4;      // row group

    float acc[8][8];
    #pragma unroll
    for (int i = 0; i < 8; i++)
        #pragma unroll
        for (int j = 0; j < 8; j++) acc[i][j] = 0.0f;

    for (int k0 = 0; k0 < F; k0 += 16) {
        // stage X tile (128 rows x 16 k), transposed to Xs[kk][row]
        #pragma unroll
        for (int i = 0; i < 2; i++) {
            int li  = t + i * 256;      // 0..511
            int row = li >> 2;          // 0..127
            int kq  = li & 3;           // 0..3
            int gr  = brow + row;
            float4 v = make_float4(0.f, 0.f, 0.f, 0.f);
            if (gr < NN) v = *(const float4*)&X[(size_t)gr * F + k0 + kq * 4];
            Xs[kq * 4 + 0][row] = v.x;
            Xs[kq * 4 + 1][row] = v.y;
            Xs[kq * 4 + 2][row] = v.z;
            Xs[kq * 4 + 3][row] = v.w;
        }
        // stage W tile (128 j x 16 k), transposed to Ws[kk][j]
        #pragma unroll
        for (int i = 0; i < 2; i++) {
            int li = t + i * 256;
            int j  = li >> 2;
            int kq = li & 3;
            float4 v = *(const float4*)&W[(size_t)j * F + k0 + kq * 4];
            Ws[kq * 4 + 0][j] = v.x;
            Ws[kq * 4 + 1][j] = v.y;
            Ws[kq * 4 + 2][j] = v.z;
            Ws[kq * 4 + 3][j] = v.w;
        }
        __syncthreads();

        #pragma unroll
        for (int kk = 0; kk < 16; kk++) {
            float4 a0 = *(const float4*)&Xs[kk][ty * 4];
            float4 a1 = *(const float4*)&Xs[kk][64 + ty * 4];
            float4 b0 = *(const float4*)&Ws[kk][tx * 4];
            float4 b1 = *(const float4*)&Ws[kk][64 + tx * 4];
            float a[8] = {a0.x, a0.y, a0.z, a0.w, a1.x, a1.y, a1.z, a1.w};
            float b[8] = {b0.x, b0.y, b0.z, b0.w, b1.x, b1.y, b1.z, b1.w};
            #pragma unroll
            for (int i = 0; i < 8; i++)
                #pragma unroll
                for (int j = 0; j < 8; j++)
                    acc[i][j] += a[i] * b[j];
        }
        __syncthreads();
    }

    #pragma unroll
    for (int i = 0; i < 8; i++) {
        int row = (i < 4) ? (ty * 4 + i) : (64 + ty * 4 + (i - 4));
        int gr = brow + row;
        if (gr < NN) {
            float s = rsqrtf(g_deg[gr]);
            float4 o0 = make_float4(acc[i][0] * s, acc[i][1] * s,
                                    acc[i][2] * s, acc[i][3] * s);
            float4 o1 = make_float4(acc[i][4] * s, acc[i][5] * s,
                                    acc[i][6] * s, acc[i][7] * s);
            *(float4*)&g_xs[(size_t)gr * F + tx * 4]      = o0;
            *(float4*)&g_xs[(size_t)gr * F + 64 + tx * 4] = o1;
        }
    }
}

// ---------------------------------------------------------------------------
// Gather: one warp per destination row.
// out[r] = dinv[r] * ( g_xs[r] + sum_{c in csr bucket r} g_xs[c] )
// ---------------------------------------------------------------------------
__device__ __forceinline__ float4 f4add(float4 a, float4 b) {
    return make_float4(a.x + b.x, a.y + b.y, a.z + b.z, a.w + b.w);
}

__global__ void gather_kernel(float* __restrict__ out) {
    int gw   = (blockIdx.x * blockDim.x + threadIdx.x) >> 5;  // global warp = row
    int lane = threadIdx.x & 31;
    if (gw >= NN) return;
    int r = gw;

    const float4* xs4 = (const float4*)g_xs;
    int start = g_offs[r];
    int end   = g_offs[r + 1];

    float4 acc = xs4[(size_t)r * 32 + lane];   // self loop

    for (int base = start; base < end; base += 32) {
        int n = min(32, end - base);
        int ce = (lane < n) ? g_csr[base + lane] : 0;
        int j = 0;
        for (; j + 4 <= n; j += 4) {
            int c0 = __shfl_sync(0xffffffffu, ce, j + 0);
            int c1 = __shfl_sync(0xffffffffu, ce, j + 1);
            int c2 = __shfl_sync(0xffffffffu, ce, j + 2);
            int c3 = __shfl_sync(0xffffffffu, ce, j + 3);
            float4 v0 = xs4[(size_t)c0 * 32 + lane];
            float4 v1 = xs4[(size_t)c1 * 32 + lane];
            float4 v2 = xs4[(size_t)c2 * 32 + lane];
            float4 v3 = xs4[(size_t)c3 * 32 + lane];
            acc = f4add(acc, f4add(f4add(v0, v1), f4add(v2, v3)));
        }
        for (; j < n; j++) {
            int c0 = __shfl_sync(0xffffffffu, ce, j);
            acc = f4add(acc, xs4[(size_t)c0 * 32 + lane]);
        }
    }

    float s = rsqrtf(g_deg[r]);
    float4 o = make_float4(acc.x * s, acc.y * s, acc.z * s, acc.w * s);
    ((float4*)out)[(size_t)r * 32 + lane] = o;
}

// ---------------------------------------------------------------------------
extern "C" void kernel_launch(void* const* d_in, const int* in_sizes, int n_in,
                              void* d_out, int out_size) {
    const float* X  = (const float*)d_in[0];
    const float* W  = (const float*)d_in[1];
    const void*  ei = d_in[2];
    int E = in_sizes[2] / 2;
    float* out = (float*)d_out;

    detect_kernel<<<1, 32>>>((const long long*)ei);
    init_kernel<<<(NN + 255) / 256, 256>>>();
    hist_kernel<<<(E + 255) / 256, 256>>>(ei, E);
    gemm_kernel<<<(NN + 127) / 128, 256>>>(X, W);
    scan_part_kernel<<<NB, 256>>>();
    scan_top_kernel<<<1, 512>>>();
    scan_final_kernel<<<NB, 256>>>();
    fill_kernel<<<(E + 255) / 256, 256>>>(ei, E);
    gather_kernel<<<(NN * 32 + 255) / 256, 256>>>(out);
}

// round 4
// speedup vs baseline: 2.2456x; 1.2805x over previous
#include <cuda_runtime.h>
#include <cstdint>

#define NN   100000
#define F    128
#define EMAX 1700000
#define NB   ((NN + 255) / 256)   // 391 scan blocks
#define NSTRIPS (NN / 16)         // 6250 (NN divisible by 16)
#define WS_PAD 132
#define WS_BYTES (128 * WS_PAD * 4)   // 67584

// ---- scratch (no cudaMalloc allowed) --------------------------------------
__device__ float g_xs[(size_t)NN * F];   // dinv[i] * (X[i] @ W^T)   (51.2 MB)
__device__ float g_deg[NN];              // 1 + count(col)
__device__ int   g_cnt[NN];              // count(row)  (CSR bucket sizes)
__device__ int   g_cur[NN];              // CSR fill cursors
__device__ int   g_offs[NN + 1];         // CSR offsets
__device__ int   g_part[NB];             // scan partials
__device__ int   g_partx[NB];            // exclusive-scanned partials
__device__ int   g_csr[EMAX];            // CSR column indices
__device__ int   g_is64;

// ---------------------------------------------------------------------------
// int64 vs int32 edge_index sniffing (deterministic on input bytes).
// ---------------------------------------------------------------------------
__global__ void detect_kernel(const long long* __restrict__ ei) {
    if (blockIdx.x == 0 && threadIdx.x == 0) {
        int is64 = 1;
        #pragma unroll 1
        for (int i = 0; i < 64; i++) {
            long long v = ei[i];
            if (v < 0 || v >= (long long)NN) { is64 = 0; break; }
        }
        g_is64 = is64;
    }
}

__device__ __forceinline__ int load_idx(const void* ei, long long i, int is64) {
    if (is64) return (int)((const long long*)ei)[i];
    return ((const int*)ei)[i];
}

// ---------------------------------------------------------------------------
__global__ void init_kernel() {
    int i = blockIdx.x * blockDim.x + threadIdx.x;
    if (i < NN) { g_deg[i] = 1.0f; g_cnt[i] = 0; g_cur[i] = 0; }
}

__global__ void hist_kernel(const void* __restrict__ ei, int E) {
    int e = blockIdx.x * blockDim.x + threadIdx.x;
    if (e >= E) return;
    int is64 = g_is64;
    int r = load_idx(ei, e, is64);
    int c = load_idx(ei, (long long)E + e, is64);
    atomicAdd(&g_deg[c], 1.0f);
    atomicAdd(&g_cnt[r], 1);
}

// ---------------------------------------------------------------------------
// 3-kernel exclusive scan of g_cnt -> g_offs
// ---------------------------------------------------------------------------
__global__ void scan_part_kernel() {
    __shared__ int sm[256];
    int t = threadIdx.x;
    int i = blockIdx.x * 256 + t;
    sm[t] = (i < NN) ? g_cnt[i] : 0;
    __syncthreads();
    for (int s = 128; s > 0; s >>= 1) {
        if (t < s) sm[t] += sm[t + s];
        __syncthreads();
    }
    if (t == 0) g_part[blockIdx.x] = sm[0];
}

__global__ void scan_top_kernel() {
    __shared__ int sm[512];
    int t = threadIdx.x;
    int v = (t < NB) ? g_part[t] : 0;
    sm[t] = v;
    __syncthreads();
    for (int off = 1; off < 512; off <<= 1) {
        int add = (t >= off) ? sm[t - off] : 0;
        __syncthreads();
        sm[t] += add;
        __syncthreads();
    }
    if (t < NB) g_partx[t] = sm[t] - v;           // exclusive
    if (t == NB - 1) g_offs[NN] = sm[t];          // total = E
}

__global__ void scan_final_kernel() {
    __shared__ int sm[256];
    int t = threadIdx.x;
    int i = blockIdx.x * 256 + t;
    int v = (i < NN) ? g_cnt[i] : 0;
    sm[t] = v;
    __syncthreads();
    for (int off = 1; off < 256; off <<= 1) {
        int add = (t >= off) ? sm[t - off] : 0;
        __syncthreads();
        sm[t] += add;
        __syncthreads();
    }
    if (i < NN) g_offs[i] = g_partx[blockIdx.x] + sm[t] - v;  // exclusive
}

__global__ void fill_kernel(const void* __restrict__ ei, int E) {
    int e = blockIdx.x * blockDim.x + threadIdx.x;
    if (e >= E) return;
    int is64 = g_is64;
    int r = load_idx(ei, e, is64);
    int c = load_idx(ei, (long long)E + e, is64);
    int pos = atomicAdd(&g_cur[r], 1);
    g_csr[g_offs[r] + pos] = c;
}

// ---------------------------------------------------------------------------
// TF32 tensor-core GEMM: g_xs[i] = rsqrt(deg[i]) * (X[i] @ W^T)
// mma.sync.m16n8k8.row.col tf32. One warp = one 16-row x 128-col strip.
// W staged per block into padded smem (conflict-free B-fragment reads),
// pre-rounded to tf32. A fragments come straight from gmem (L1 resident).
// ---------------------------------------------------------------------------
__device__ __forceinline__ unsigned int f2tf32(float x) {
    unsigned int r;
    asm("cvt.rna.tf32.f32 %0, %1;" : "=r"(r) : "f"(x));
    return r;
}

__global__ void __launch_bounds__(256)
gemm_tf32_kernel(const float* __restrict__ X, const float* __restrict__ W) {
    extern __shared__ float Ws[];   // [128][WS_PAD], tf32-rounded W

    int t = threadIdx.x;
    // Stage W: 4096 float4s, 16 per thread, cvt.rna to tf32.
    #pragma unroll
    for (int i = 0; i < 16; i++) {
        int idx = t + i * 256;          // float4 index 0..4095
        int n   = idx >> 5;             // W row (output feature)
        int kq  = idx & 31;             // float4 within row
        float4 v = *(const float4*)&W[(size_t)n * F + kq * 4];
        unsigned int* dst = (unsigned int*)&Ws[n * WS_PAD + kq * 4];
        dst[0] = f2tf32(v.x);
        dst[1] = f2tf32(v.y);
        dst[2] = f2tf32(v.z);
        dst[3] = f2tf32(v.w);
    }
    __syncthreads();

    int warp  = t >> 5;
    int lane  = t & 31;
    int strip = blockIdx.x * 8 + warp;
    if (strip >= NSTRIPS) return;
    int brow = strip * 16;
    int gid = lane >> 2;   // 0..7
    int tig = lane & 3;    // 0..3

    float d[16][4];
    #pragma unroll
    for (int nt = 0; nt < 16; nt++)
        #pragma unroll
        for (int j = 0; j < 4; j++) d[nt][j] = 0.0f;

    const float* Xr0 = X + (size_t)(brow + gid) * F;
    const float* Xr1 = X + (size_t)(brow + gid + 8) * F;

    #pragma unroll 4
    for (int k0 = 0; k0 < F; k0 += 8) {
        unsigned int a0 = f2tf32(__ldg(&Xr0[k0 + tig]));
        unsigned int a1 = f2tf32(__ldg(&Xr1[k0 + tig]));
        unsigned int a2 = f2tf32(__ldg(&Xr0[k0 + tig + 4]));
        unsigned int a3 = f2tf32(__ldg(&Xr1[k0 + tig + 4]));

        #pragma unroll
        for (int nt = 0; nt < 16; nt++) {
            const unsigned int* wp =
                (const unsigned int*)&Ws[(nt * 8 + gid) * WS_PAD + k0 + tig];
            unsigned int b0 = wp[0];
            unsigned int b1 = wp[4];
            asm volatile(
                "mma.sync.aligned.m16n8k8.row.col.f32.tf32.tf32.f32 "
                "{%0,%1,%2,%3}, {%4,%5,%6,%7}, {%8,%9}, {%0,%1,%2,%3};"
                : "+f"(d[nt][0]), "+f"(d[nt][1]), "+f"(d[nt][2]), "+f"(d[nt][3])
                : "r"(a0), "r"(a1), "r"(a2), "r"(a3), "r"(b0), "r"(b1));
        }
    }

    // Epilogue: scale by rsqrt(deg) and store.
    int r0 = brow + gid;
    int r1 = brow + gid + 8;
    float s0 = rsqrtf(g_deg[r0]);
    float s1 = rsqrtf(g_deg[r1]);
    #pragma unroll
    for (int nt = 0; nt < 16; nt++) {
        float2 lo = make_float2(d[nt][0] * s0, d[nt][1] * s0);
        float2 hi = make_float2(d[nt][2] * s1, d[nt][3] * s1);
        *(float2*)&g_xs[(size_t)r0 * F + nt * 8 + tig * 2] = lo;
        *(float2*)&g_xs[(size_t)r1 * F + nt * 8 + tig * 2] = hi;
    }
}

// ---------------------------------------------------------------------------
// Gather: one warp per destination row.
// out[r] = dinv[r] * ( g_xs[r] + sum_{c in csr bucket r} g_xs[c] )
// ---------------------------------------------------------------------------
__device__ __forceinline__ float4 f4add(float4 a, float4 b) {
    return make_float4(a.x + b.x, a.y + b.y, a.z + b.z, a.w + b.w);
}

__global__ void gather_kernel(float* __restrict__ out) {
    int gw   = (blockIdx.x * blockDim.x + threadIdx.x) >> 5;  // row
    int lane = threadIdx.x & 31;
    if (gw >= NN) return;
    int r = gw;

    const float4* xs4 = (const float4*)g_xs;
    int start = g_offs[r];
    int end   = g_offs[r + 1];

    float4 acc = xs4[(size_t)r * 32 + lane];   // self loop

    for (int base = start; base < end; base += 32) {
        int n = min(32, end - base);
        int ce = (lane < n) ? g_csr[base + lane] : 0;
        int j = 0;
        for (; j + 4 <= n; j += 4) {
            int c0 = __shfl_sync(0xffffffffu, ce, j + 0);
            int c1 = __shfl_sync(0xffffffffu, ce, j + 1);
            int c2 = __shfl_sync(0xffffffffu, ce, j + 2);
            int c3 = __shfl_sync(0xffffffffu, ce, j + 3);
            float4 v0 = xs4[(size_t)c0 * 32 + lane];
            float4 v1 = xs4[(size_t)c1 * 32 + lane];
            float4 v2 = xs4[(size_t)c2 * 32 + lane];
            float4 v3 = xs4[(size_t)c3 * 32 + lane];
            acc = f4add(acc, f4add(f4add(v0, v1), f4add(v2, v3)));
        }
        for (; j < n; j++) {
            int c0 = __shfl_sync(0xffffffffu, ce, j);
            acc = f4add(acc, xs4[(size_t)c0 * 32 + lane]);
        }
    }

    float s = rsqrtf(g_deg[r]);
    float4 o = make_float4(acc.x * s, acc.y * s, acc.z * s, acc.w * s);
    ((float4*)out)[(size_t)r * 32 + lane] = o;
}

// ---------------------------------------------------------------------------
extern "C" void kernel_launch(void* const* d_in, const int* in_sizes, int n_in,
                              void* d_out, int out_size) {
    const float* X  = (const float*)d_in[0];
    const float* W  = (const float*)d_in[1];
    const void*  ei = d_in[2];
    int E = in_sizes[2] / 2;
    float* out = (float*)d_out;

    static int smem_set = 0;
    if (!smem_set) {
        cudaFuncSetAttribute(gemm_tf32_kernel,
                             cudaFuncAttributeMaxDynamicSharedMemorySize,
                             WS_BYTES);
        smem_set = 1;
    }

    detect_kernel<<<1, 32>>>((const long long*)ei);
    init_kernel<<<(NN + 255) / 256, 256>>>();
    hist_kernel<<<(E + 255) / 256, 256>>>(ei, E);
    gemm_tf32_kernel<<<(NSTRIPS + 7) / 8, 256, WS_BYTES>>>(X, W);
    scan_part_kernel<<<NB, 256>>>();
    scan_top_kernel<<<1, 512>>>();
    scan_final_kernel<<<NB, 256>>>();
    fill_kernel<<<(E + 255) / 256, 256>>>(ei, E);
    gather_kernel<<<(NN * 32 + 255) / 256, 256>>>(out);
}

// round 5
// speedup vs baseline: 2.3664x; 1.0538x over previous
#include <cuda_runtime.h>
#include <cstdint>

#define NN   100000
#define F    128
#define EMAX 1700000
#define NB   ((NN + 255) / 256)   // 391 scan blocks
#define NSTRIPS (NN / 16)         // 6250
#define WS_PAD 132
#define WS_BYTES (128 * WS_PAD * 4)   // 67584

// ---- scratch (no cudaMalloc allowed) --------------------------------------
__device__ float g_xs[(size_t)NN * F];   // raw X @ W^T (51.2 MB)
__device__ float g_deg[NN];              // 1 + count(col)
__device__ int   g_cnt[NN];              // count(row)  (CSR bucket sizes)
__device__ int   g_cur[NN];              // CSR fill cursors
__device__ int   g_offs[NN + 1];         // CSR offsets
__device__ int   g_part[NB];             // scan partials
__device__ int   g_partx[NB];            // exclusive-scanned partials
__device__ int   g_csr[EMAX];            // CSR column indices
__device__ int   g_is64;

// ---------------------------------------------------------------------------
// int64 vs int32 edge_index sniffing (deterministic on input bytes).
// ---------------------------------------------------------------------------
__global__ void detect_kernel(const long long* __restrict__ ei) {
    if (blockIdx.x == 0 && threadIdx.x == 0) {
        int is64 = 1;
        #pragma unroll 1
        for (int i = 0; i < 64; i++) {
            long long v = ei[i];
            if (v < 0 || v >= (long long)NN) { is64 = 0; break; }
        }
        g_is64 = is64;
    }
}

__device__ __forceinline__ int load_idx(const void* ei, long long i, int is64) {
    if (is64) return (int)((const long long*)ei)[i];
    return ((const int*)ei)[i];
}

// ---------------------------------------------------------------------------
__global__ void init_kernel() {
    int i = blockIdx.x * blockDim.x + threadIdx.x;
    if (i < NN) { g_deg[i] = 1.0f; g_cnt[i] = 0; g_cur[i] = 0; }
}

__global__ void hist_kernel(const void* __restrict__ ei, int E) {
    int e = blockIdx.x * blockDim.x + threadIdx.x;
    if (e >= E) return;
    int is64 = g_is64;
    int r = load_idx(ei, e, is64);
    int c = load_idx(ei, (long long)E + e, is64);
    atomicAdd(&g_deg[c], 1.0f);
    atomicAdd(&g_cnt[r], 1);
}

// ---------------------------------------------------------------------------
// 3-kernel exclusive scan of g_cnt -> g_offs
// ---------------------------------------------------------------------------
__global__ void scan_part_kernel() {
    __shared__ int sm[256];
    int t = threadIdx.x;
    int i = blockIdx.x * 256 + t;
    sm[t] = (i < NN) ? g_cnt[i] : 0;
    __syncthreads();
    for (int s = 128; s > 0; s >>= 1) {
        if (t < s) sm[t] += sm[t + s];
        __syncthreads();
    }
    if (t == 0) g_part[blockIdx.x] = sm[0];
}

__global__ void scan_top_kernel() {
    __shared__ int sm[512];
    int t = threadIdx.x;
    int v = (t < NB) ? g_part[t] : 0;
    sm[t] = v;
    __syncthreads();
    for (int off = 1; off < 512; off <<= 1) {
        int add = (t >= off) ? sm[t - off] : 0;
        __syncthreads();
        sm[t] += add;
        __syncthreads();
    }
    if (t < NB) g_partx[t] = sm[t] - v;           // exclusive
    if (t == NB - 1) g_offs[NN] = sm[t];          // total = E
}

__global__ void scan_final_kernel() {
    __shared__ int sm[256];
    int t = threadIdx.x;
    int i = blockIdx.x * 256 + t;
    int v = (i < NN) ? g_cnt[i] : 0;
    sm[t] = v;
    __syncthreads();
    for (int off = 1; off < 256; off <<= 1) {
        int add = (t >= off) ? sm[t - off] : 0;
        __syncthreads();
        sm[t] += add;
        __syncthreads();
    }
    if (i < NN) g_offs[i] = g_partx[blockIdx.x] + sm[t] - v;  // exclusive
}

__global__ void fill_kernel(const void* __restrict__ ei, int E) {
    int e = blockIdx.x * blockDim.x + threadIdx.x;
    if (e >= E) return;
    int is64 = g_is64;
    int r = load_idx(ei, e, is64);
    int c = load_idx(ei, (long long)E + e, is64);
    int pos = atomicAdd(&g_cur[r], 1);
    g_csr[g_offs[r] + pos] = c;
}

// ---------------------------------------------------------------------------
// TF32 tensor-core GEMM: g_xs[i] = X[i] @ W^T   (raw, no deg dependency).
// mma.sync.m16n8k8.row.col tf32. One warp = one 16-row x 128-col strip.
// ---------------------------------------------------------------------------
__device__ __forceinline__ unsigned int f2tf32(float x) {
    unsigned int r;
    asm("cvt.rna.tf32.f32 %0, %1;" : "=r"(r) : "f"(x));
    return r;
}

__global__ void __launch_bounds__(256)
gemm_tf32_kernel(const float* __restrict__ X, const float* __restrict__ W) {
    extern __shared__ float Ws[];   // [128][WS_PAD], tf32-rounded W

    int t = threadIdx.x;
    #pragma unroll
    for (int i = 0; i < 16; i++) {
        int idx = t + i * 256;          // float4 index 0..4095
        int n   = idx >> 5;             // W row (output feature)
        int kq  = idx & 31;             // float4 within row
        float4 v = *(const float4*)&W[(size_t)n * F + kq * 4];
        unsigned int* dst = (unsigned int*)&Ws[n * WS_PAD + kq * 4];
        dst[0] = f2tf32(v.x);
        dst[1] = f2tf32(v.y);
        dst[2] = f2tf32(v.z);
        dst[3] = f2tf32(v.w);
    }
    __syncthreads();

    int warp  = t >> 5;
    int lane  = t & 31;
    int strip = blockIdx.x * 8 + warp;
    if (strip >= NSTRIPS) return;
    int brow = strip * 16;
    int gid = lane >> 2;   // 0..7
    int tig = lane & 3;    // 0..3

    float d[16][4];
    #pragma unroll
    for (int nt = 0; nt < 16; nt++)
        #pragma unroll
        for (int j = 0; j < 4; j++) d[nt][j] = 0.0f;

    const float* Xr0 = X + (size_t)(brow + gid) * F;
    const float* Xr1 = X + (size_t)(brow + gid + 8) * F;

    #pragma unroll 4
    for (int k0 = 0; k0 < F; k0 += 8) {
        unsigned int a0 = f2tf32(__ldg(&Xr0[k0 + tig]));
        unsigned int a1 = f2tf32(__ldg(&Xr1[k0 + tig]));
        unsigned int a2 = f2tf32(__ldg(&Xr0[k0 + tig + 4]));
        unsigned int a3 = f2tf32(__ldg(&Xr1[k0 + tig + 4]));

        #pragma unroll
        for (int nt = 0; nt < 16; nt++) {
            const unsigned int* wp =
                (const unsigned int*)&Ws[(nt * 8 + gid) * WS_PAD + k0 + tig];
            unsigned int b0 = wp[0];
            unsigned int b1 = wp[4];
            asm volatile(
                "mma.sync.aligned.m16n8k8.row.col.f32.tf32.tf32.f32 "
                "{%0,%1,%2,%3}, {%4,%5,%6,%7}, {%8,%9}, {%0,%1,%2,%3};"
                : "+f"(d[nt][0]), "+f"(d[nt][1]), "+f"(d[nt][2]), "+f"(d[nt][3])
                : "r"(a0), "r"(a1), "r"(a2), "r"(a3), "r"(b0), "r"(b1));
        }
    }

    int r0 = brow + gid;
    int r1 = brow + gid + 8;
    #pragma unroll
    for (int nt = 0; nt < 16; nt++) {
        float2 lo = make_float2(d[nt][0], d[nt][1]);
        float2 hi = make_float2(d[nt][2], d[nt][3]);
        *(float2*)&g_xs[(size_t)r0 * F + nt * 8 + tig * 2] = lo;
        *(float2*)&g_xs[(size_t)r1 * F + nt * 8 + tig * 2] = hi;
    }
}

// ---------------------------------------------------------------------------
// Gather: one warp per destination row.
// out[r] = dinv[r] * ( dinv[r]*xs[r] + sum_{c in bucket r} dinv[c]*xs[c] )
// ---------------------------------------------------------------------------
__global__ void gather_kernel(float* __restrict__ out) {
    int gw   = (blockIdx.x * blockDim.x + threadIdx.x) >> 5;  // row
    int lane = threadIdx.x & 31;
    if (gw >= NN) return;
    int r = gw;

    const float4* xs4 = (const float4*)g_xs;
    int start = g_offs[r];
    int end   = g_offs[r + 1];
    float sr  = rsqrtf(g_deg[r]);

    float4 v = xs4[(size_t)r * 32 + lane];   // self loop
    float4 acc = make_float4(sr * v.x, sr * v.y, sr * v.z, sr * v.w);

    for (int base = start; base < end; base += 32) {
        int n = min(32, end - base);
        int   ce = 0;
        float se = 0.0f;
        if (lane < n) {
            ce = g_csr[base + lane];
            se = rsqrtf(g_deg[ce]);
        }
        int j = 0;
        for (; j + 4 <= n; j += 4) {
            int   c0 = __shfl_sync(0xffffffffu, ce, j + 0);
            int   c1 = __shfl_sync(0xffffffffu, ce, j + 1);
            int   c2 = __shfl_sync(0xffffffffu, ce, j + 2);
            int   c3 = __shfl_sync(0xffffffffu, ce, j + 3);
            float s0 = __shfl_sync(0xffffffffu, se, j + 0);
            float s1 = __shfl_sync(0xffffffffu, se, j + 1);
            float s2 = __shfl_sync(0xffffffffu, se, j + 2);
            float s3 = __shfl_sync(0xffffffffu, se, j + 3);
            float4 v0 = xs4[(size_t)c0 * 32 + lane];
            float4 v1 = xs4[(size_t)c1 * 32 + lane];
            float4 v2 = xs4[(size_t)c2 * 32 + lane];
            float4 v3 = xs4[(size_t)c3 * 32 + lane];
            acc.x += s0 * v0.x; acc.y += s0 * v0.y; acc.z += s0 * v0.z; acc.w += s0 * v0.w;
            acc.x += s1 * v1.x; acc.y += s1 * v1.y; acc.z += s1 * v1.z; acc.w += s1 * v1.w;
            acc.x += s2 * v2.x; acc.y += s2 * v2.y; acc.z += s2 * v2.z; acc.w += s2 * v2.w;
            acc.x += s3 * v3.x; acc.y += s3 * v3.y; acc.z += s3 * v3.z; acc.w += s3 * v3.w;
        }
        for (; j < n; j++) {
            int   c0 = __shfl_sync(0xffffffffu, ce, j);
            float s0 = __shfl_sync(0xffffffffu, se, j);
            float4 v0 = xs4[(size_t)c0 * 32 + lane];
            acc.x += s0 * v0.x; acc.y += s0 * v0.y;
            acc.z += s0 * v0.z; acc.w += s0 * v0.w;
        }
    }

    float4 o = make_float4(acc.x * sr, acc.y * sr, acc.z * sr, acc.w * sr);
    ((float4*)out)[(size_t)r * 32 + lane] = o;
}

// ---------------------------------------------------------------------------
extern "C" void kernel_launch(void* const* d_in, const int* in_sizes, int n_in,
                              void* d_out, int out_size) {
    const float* X  = (const float*)d_in[0];
    const float* W  = (const float*)d_in[1];
    const void*  ei = d_in[2];
    int E = in_sizes[2] / 2;
    float* out = (float*)d_out;

    // One-time resource setup (first call is the uncaptured correctness run).
    static cudaStream_t s2 = nullptr;
    static cudaEvent_t  evFork = nullptr, evJoin = nullptr;
    if (!s2) {
        cudaFuncSetAttribute(gemm_tf32_kernel,
                             cudaFuncAttributeMaxDynamicSharedMemorySize,
                             WS_BYTES);
        cudaStreamCreateWithFlags(&s2, cudaStreamNonBlocking);
        cudaEventCreateWithFlags(&evFork, cudaEventDisableTiming);
        cudaEventCreateWithFlags(&evJoin, cudaEventDisableTiming);
    }

    // Main stream: edge pipeline.  Side stream s2: GEMM (independent).
    detect_kernel<<<1, 32>>>((const long long*)ei);

    cudaEventRecord(evFork, 0);
    cudaStreamWaitEvent(s2, evFork, 0);
    gemm_tf32_kernel<<<(NSTRIPS + 7) / 8, 256, WS_BYTES, s2>>>(X, W);

    init_kernel<<<(NN + 255) / 256, 256>>>();
    hist_kernel<<<(E + 255) / 256, 256>>>(ei, E);
    scan_part_kernel<<<NB, 256>>>();
    scan_top_kernel<<<1, 512>>>();
    scan_final_kernel<<<NB, 256>>>();
    fill_kernel<<<(E + 255) / 256, 256>>>(ei, E);

    cudaEventRecord(evJoin, s2);
    cudaStreamWaitEvent(0, evJoin, 0);
    gather_kernel<<<(NN * 32 + 255) / 256, 256>>>(out);
}